// round 15
// baseline (speedup 1.0000x reference)
#include <cuda_runtime.h>
#include <cstdint>
#include <math.h>

#define WTOT 4096
#define SUB 64                  // rows per subtile
#define NSUB 4                  // subtiles per block
#define ROWS_PER_BLK (SUB * NSUB)       // 256
#define HDIM 128
#define BATCH 64
#define NBLKG (WTOT / ROWS_PER_BLK)     // 16 block-groups per batch
#define NATT (BATCH * NBLKG)            // 1024 attention blocks
#define NPRE 512                        // tail pre blocks

__device__ __align__(16) float g_pvec[BATCH * NBLKG * HDIM];  // 512 KB
__device__ __align__(16) float g_psum[BATCH * NBLKG];
__device__ __align__(16) float g_pre0[BATCH * 512];
__device__ __align__(16) float g_pre1[BATCH * 512];

__device__ __forceinline__ float warp_sum(float p) {
    #pragma unroll
    for (int o = 16; o > 0; o >>= 1) p += __shfl_down_sync(0xffffffffu, p, o);
    return p;
}

__device__ __forceinline__ float sigmoidf_(float x) {
    return 1.0f / (1.0f + expf(-x));
}

__device__ __forceinline__ float dot4(float4 a, float4 b) {
    return a.x * b.x + a.y * b.y + a.z * b.z + a.w * b.w;
}

__device__ __forceinline__ void cp16(void* smem_dst, const void* gmem_src) {
    unsigned int s = (unsigned int)__cvta_generic_to_shared(smem_dst);
    asm volatile("cp.async.cg.shared.global [%0], [%1], 16;" :: "r"(s), "l"(gmem_src));
}
#define CP_COMMIT() asm volatile("cp.async.commit_group;")
#define CP_WAIT(n)  asm volatile("cp.async.wait_group %0;" :: "n"(n))

// score 64 rows: 8 warps x 8 rows, interleaved shfl chains
__device__ __forceinline__ void score_rows8(
    const float* tile, float4 wv, float bias, float* s_sh, int wrp, int lane)
{
    float acc[8];
    #pragma unroll
    for (int t = 0; t < 8; t++) {
        const float4 rv = *(const float4*)&tile[(wrp + 8 * t) * HDIM + lane * 4];
        acc[t] = dot4(rv, wv);
    }
    #pragma unroll
    for (int o = 16; o > 0; o >>= 1) {
        #pragma unroll
        for (int t = 0; t < 8; t++)
            acc[t] += __shfl_down_sync(0xffffffffu, acc[t], o);
    }
    if (lane == 0) {
        #pragma unroll
        for (int t = 0; t < 8; t++)
            s_sh[wrp + 8 * t] = acc[t] + bias;
    }
}

// ---------------------------------------------------------------------------
// Attention: 1024 streaming blocks, 4 chunks each, double-buffered cp.async.
// Blocks >= NATT: hh-gate precompute in the drain wave.
// ---------------------------------------------------------------------------
__global__ void __launch_bounds__(256) attn_pre_kernel(
    const float* __restrict__ enc,
    const float* __restrict__ h0,
    const float* __restrict__ c0,
    const float* __restrict__ attW,
    const float* __restrict__ attb,
    const float* __restrict__ W_hh0,
    const float* __restrict__ b_ih0, const float* __restrict__ b_hh0,
    const float* __restrict__ W_hh1,
    const float* __restrict__ b_ih1, const float* __restrict__ b_hh1)
{
    const int tid  = threadIdx.x;
    const int lane = tid & 31;
    const int wrp  = tid >> 5;

    if (blockIdx.x >= NATT) {
        const int p  = blockIdx.x - NATT;
        const int b  = p >> 3;
        const int k0 = (p & 7) * 64;
        const float4 hv0 = ((const float4*)(h0 + b * HDIM))[lane];
        const float4 hv1 = ((const float4*)(h0 + BATCH * HDIM + b * HDIM))[lane];
        #pragma unroll 4
        for (int t = 0; t < 8; t++) {
            const int k = k0 + wrp * 8 + t;
            float p0 = dot4(((const float4*)(W_hh0 + k * HDIM))[lane], hv0);
            p0 = warp_sum(p0);
            if (lane == 0) g_pre0[b * 512 + k] = p0 + b_ih0[k] + b_hh0[k];
        }
        #pragma unroll 4
        for (int t = 0; t < 8; t++) {
            const int k = k0 + wrp * 8 + t;
            float p1 = dot4(((const float4*)(W_hh1 + k * HDIM))[lane], hv1);
            p1 = warp_sum(p1);
            if (lane == 0) g_pre1[b * 512 + k] = p1 + b_ih1[k] + b_hh1[k];
        }
        return;
    }

    extern __shared__ __align__(16) float dyn[];    // 2 x 64x128 = 64 KB
    float* tbuf0 = dyn;
    float* tbuf1 = dyn + SUB * HDIM;

    __shared__ float s_sh[SUB];
    __shared__ float e_sh[SUB];
    __shared__ float red[4];
    __shared__ float bias_sh;
    __shared__ float sprev_arr[NSUB + 1];
    __shared__ float part2[2][HDIM];

    const int b      = blockIdx.x >> 4;       // NBLKG = 16
    const int g      = blockIdx.x & 15;
    const int start0 = g * ROWS_PER_BLK;
    const float* encb = enc + ((size_t)b * WTOT) * HDIM;

    // Prologue: issue chunk 0 load.
    {
        const float4* src = (const float4*)(encb + (size_t)start0 * HDIM);
        float4* dst = (float4*)tbuf0;
        #pragma unroll
        for (int i = 0; i < 8; i++) cp16(&dst[tid + 256 * i], &src[tid + 256 * i]);
        CP_COMMIT();
    }

    const float4 wv = ((const float4*)attW)[lane];
    float4 vprev = make_float4(0.f, 0.f, 0.f, 0.f);
    if (wrp == 0 && start0 > 0)
        vprev = ((const float4*)(encb + (size_t)(start0 - 1) * HDIM))[lane];

    // Bias: (h1*c1).wa_st + att_b (overlaps the first transfer)
    if (tid < HDIM) {
        float p = h0[BATCH * HDIM + b * HDIM + tid]
                * c0[BATCH * HDIM + b * HDIM + tid]
                * attW[HDIM + tid];
        p = warp_sum(p);
        if (lane == 0) red[wrp] = p;
    }
    __syncthreads();
    if (tid == 0) bias_sh = red[0] + red[1] + red[2] + red[3] + attb[0];
    __syncthreads();
    const float bias = bias_sh;

    if (wrp == 0 && start0 > 0) {
        float s = warp_sum(dot4(vprev, wv));
        if (lane == 0) sprev_arr[0] = s + bias;
    }

    const int h = tid & 127, grp = tid >> 7;
    float acc_v  = 0.0f;     // weighted-sum accumulator (column h, row-half grp)
    float es_acc = 0.0f;     // exp-sum accumulator (warp 0)

    #pragma unroll
    for (int j = 0; j < NSUB; j++) {
        const float* tile = (j & 1) ? tbuf1 : tbuf0;

        CP_WAIT(0);
        __syncthreads();            // tile(j) ready; wsum(j-1) complete

        // Issue chunk j+1 into the other buffer (transfers during compute).
        if (j < NSUB - 1) {
            const float4* src = (const float4*)(encb + (size_t)(start0 + (j + 1) * SUB) * HDIM);
            float4* dst = (float4*)((j & 1) ? tbuf0 : tbuf1);
            #pragma unroll
            for (int i = 0; i < 8; i++) cp16(&dst[tid + 256 * i], &src[tid + 256 * i]);
            CP_COMMIT();
        }

        score_rows8(tile, wv, bias, s_sh, wrp, lane);
        __syncthreads();            // s_sh ready

        if (tid < SUB) {
            float logit;
            if (tid == 0) logit = (start0 == 0 && j == 0) ? 0.0f : sprev_arr[j];
            else          logit = s_sh[tid - 1];
            e_sh[tid] = expf(logit);
        } else if (tid == SUB) {
            sprev_arr[j + 1] = s_sh[SUB - 1];   // next chunk's carried score
        }
        __syncthreads();            // e_sh ready

        #pragma unroll
        for (int r0 = 0; r0 < 32; r0++) {
            const int r = grp * 32 + r0;
            acc_v += e_sh[r] * tile[r * HDIM + h];
        }
        if (wrp == 0) es_acc += e_sh[lane] + e_sh[lane + 32];
    }

    part2[grp][h] = acc_v;
    __syncthreads();
    if (tid < HDIM)
        g_pvec[((size_t)b * NBLKG + g) * HDIM + tid] = part2[0][tid] + part2[1][tid];
    if (wrp == 0) {
        float es = warp_sum(es_acc);
        if (lane == 0) g_psum[b * NBLKG + g] = es;
    }
}

// ---------------------------------------------------------------------------
// Pipelined coalesced warp-dots: 16 gates per warp, K=128.
// ---------------------------------------------------------------------------
__device__ __forceinline__ void lstm_gates(
    const float* __restrict__ W, const float4 xv,
    const float* __restrict__ pre_sh, float* gate_sh,
    int wrp, int lane)
{
    const int kbase = wrp * 16;
    float4 w[2][4];
    #pragma unroll
    for (int t = 0; t < 4; t++)
        w[0][t] = ((const float4*)(W + (kbase + t) * HDIM))[lane];
    #pragma unroll
    for (int g = 0; g < 4; g++) {
        if (g < 3) {
            #pragma unroll
            for (int t = 0; t < 4; t++)
                w[(g + 1) & 1][t] =
                    ((const float4*)(W + (kbase + (g + 1) * 4 + t) * HDIM))[lane];
        }
        float acc[4];
        #pragma unroll
        for (int t = 0; t < 4; t++) acc[t] = dot4(w[g & 1][t], xv);
        #pragma unroll
        for (int o = 16; o > 0; o >>= 1) {
            #pragma unroll
            for (int t = 0; t < 4; t++)
                acc[t] += __shfl_down_sync(0xffffffffu, acc[t], o);
        }
        if (lane == 0) {
            #pragma unroll
            for (int t = 0; t < 4; t++) {
                const int k = kbase + g * 4 + t;
                gate_sh[k] = acc[t] + pre_sh[k];
            }
        }
    }
}

// ---------------------------------------------------------------------------
// Decode (R14 structure, 16 partials): one block per batch, 1024 threads.
// ---------------------------------------------------------------------------
__global__ void __launch_bounds__(1024) decode_kernel(
    const float* __restrict__ input,
    const float* __restrict__ c0,
    const float* __restrict__ inp_W, const float* __restrict__ inp_b,
    const float* __restrict__ W_ih0,
    const float* __restrict__ W_ih1,
    float* __restrict__ out)
{
    __shared__ __align__(16) float cat_sh[256];
    __shared__ __align__(16) float xin_sh[HDIM];
    __shared__ __align__(16) float h1_sh[HDIM];
    __shared__ float gate_sh[512];
    __shared__ float c0_sh[2 * HDIM];
    __shared__ float vred[8][HDIM];
    __shared__ float sarr[NBLKG];
    __shared__ float pre0_sh[512];
    __shared__ float pre1_sh[512];
    __shared__ float S_sh;

    const int b = blockIdx.x;
    const int tid = threadIdx.x, lane = tid & 31, wrp = tid >> 5;

    // Early independent loads
    if (tid < HDIM) {
        c0_sh[tid]        = c0[b * HDIM + tid];
        c0_sh[HDIM + tid] = c0[BATCH * HDIM + b * HDIM + tid];
    }
    if (tid < 512) pre0_sh[tid] = g_pre0[b * 512 + tid];
    else           pre1_sh[tid - 512] = g_pre1[b * 512 + (tid - 512)];

    // Stage 0: reduce partials — 8 groups x 2 chunks, all distinct cells.
    if (tid < NBLKG) sarr[tid] = g_psum[b * NBLKG + tid];
    {
        const int h = tid & 127, grp = tid >> 7;   // grp 0..7
        float v = 0.0f;
        #pragma unroll
        for (int c = 0; c < 2; c++)
            v += g_pvec[((size_t)b * NBLKG + grp * 2 + c) * HDIM + h];
        vred[grp][h] = v;
    }
    __syncthreads();
    float vcol = 0.0f;
    if (tid < HDIM) {
        #pragma unroll
        for (int g = 0; g < 8; g++) vcol += vred[g][tid];
    }
    if (wrp == 0) {
        float s = (lane < NBLKG) ? sarr[lane] : 0.0f;
        s = warp_sum(s);
        if (lane == 0) S_sh = s;
    }
    __syncthreads();
    if (tid < HDIM) {
        cat_sh[tid]        = vcol / S_sh;
        cat_sh[HDIM + tid] = input[b * HDIM + tid];
    }
    __syncthreads();

    // xin: 32 warps x 4 outputs, K=256.
    {
        const float4 c0v = ((const float4*)cat_sh)[lane];
        const float4 c1v = ((const float4*)cat_sh)[lane + 32];
        float4 a0[4], a1[4];
        #pragma unroll
        for (int t = 0; t < 4; t++) {
            const float4* wrow = (const float4*)(inp_W + (wrp * 4 + t) * 256);
            a0[t] = wrow[lane];
            a1[t] = wrow[lane + 32];
        }
        float acc[4];
        #pragma unroll
        for (int t = 0; t < 4; t++)
            acc[t] = dot4(a0[t], c0v) + dot4(a1[t], c1v);
        #pragma unroll
        for (int o = 16; o > 0; o >>= 1) {
            #pragma unroll
            for (int t = 0; t < 4; t++)
                acc[t] += __shfl_down_sync(0xffffffffu, acc[t], o);
        }
        if (lane == 0) {
            #pragma unroll
            for (int t = 0; t < 4; t++) {
                const int i = wrp * 4 + t;
                xin_sh[i] = acc[t] + inp_b[i];
            }
        }
    }
    __syncthreads();

    float* out_h1 = out + 8192 + b * HDIM;
    float* out_h2 = out + 16384 + b * HDIM;
    float* out_c1 = out + 24576 + b * HDIM;
    float* out_c2 = out + 32768 + b * HDIM;
    float* out_y  = out + b * HDIM;

    // LSTM layer 0
    lstm_gates(W_ih0, ((const float4*)xin_sh)[lane], pre0_sh, gate_sh, wrp, lane);
    __syncthreads();
    if (tid < HDIM) {
        const float ig = gate_sh[tid];
        const float fg = gate_sh[128 + tid];
        const float gg = gate_sh[256 + tid];
        const float og = gate_sh[384 + tid];
        const float cn = sigmoidf_(fg) * c0_sh[tid] + sigmoidf_(ig) * tanhf(gg);
        const float hn = sigmoidf_(og) * tanhf(cn);
        h1_sh[tid]  = hn;
        out_c1[tid] = cn;
        out_h1[tid] = hn;
    }
    __syncthreads();

    // LSTM layer 1
    lstm_gates(W_ih1, ((const float4*)h1_sh)[lane], pre1_sh, gate_sh, wrp, lane);
    __syncthreads();
    if (tid < HDIM) {
        const float ig = gate_sh[tid];
        const float fg = gate_sh[128 + tid];
        const float gg = gate_sh[256 + tid];
        const float og = gate_sh[384 + tid];
        const float cn = sigmoidf_(fg) * c0_sh[HDIM + tid] + sigmoidf_(ig) * tanhf(gg);
        const float hn = sigmoidf_(og) * tanhf(cn);
        out_c2[tid] = cn;
        out_h2[tid] = hn;
        out_y[tid]  = hn;
    }
}

extern "C" void kernel_launch(void* const* d_in, const int* in_sizes, int n_in,
                              void* d_out, int out_size)
{
    const float* input  = (const float*)d_in[0];
    const float* h0     = (const float*)d_in[1];
    const float* c0     = (const float*)d_in[2];
    const float* enc    = (const float*)d_in[3];
    const float* attW   = (const float*)d_in[4];
    const float* attb   = (const float*)d_in[5];
    const float* inp_W  = (const float*)d_in[6];
    const float* inp_b  = (const float*)d_in[7];
    const float* W_ih0  = (const float*)d_in[8];
    const float* W_hh0  = (const float*)d_in[9];
    const float* b_ih0  = (const float*)d_in[10];
    const float* b_hh0  = (const float*)d_in[11];
    const float* W_ih1  = (const float*)d_in[12];
    const float* W_hh1  = (const float*)d_in[13];
    const float* b_ih1  = (const float*)d_in[14];
    const float* b_hh1  = (const float*)d_in[15];
    float* out = (float*)d_out;

    const int dyn_bytes = 2 * SUB * HDIM * sizeof(float);   // 64 KB
    cudaFuncSetAttribute(attn_pre_kernel,
                         cudaFuncAttributeMaxDynamicSharedMemorySize, dyn_bytes);

    attn_pre_kernel<<<NATT + NPRE, 256, dyn_bytes>>>(
        enc, h0, c0, attW, attb,
        W_hh0, b_ih0, b_hh0, W_hh1, b_ih1, b_hh1);
    decode_kernel<<<BATCH, 1024>>>(input, c0, inp_W, inp_b, W_ih0, W_ih1, out);
}

// round 16
// speedup vs baseline: 1.0403x; 1.0403x over previous
#include <cuda_runtime.h>
#include <cstdint>
#include <math.h>

#define WTOT 4096
#define CHUNK 64
#define HDIM 128
#define BATCH 64
#define NCH (WTOT / CHUNK)      // 64 chunks of 64 rows
#define NATT (NCH * BATCH)      // 4096 attention blocks
#define NPRE 512                // pre blocks
#define NWARM 16                // L2 weight-warm blocks (very tail)

__device__ __align__(16) float g_pvec[BATCH * NCH * HDIM];  // 2 MB
__device__ __align__(16) float g_psum[BATCH * NCH];
__device__ __align__(16) float g_pre0[BATCH * 512];
__device__ __align__(16) float g_pre1[BATCH * 512];

__device__ __forceinline__ float warp_sum(float p) {
    #pragma unroll
    for (int o = 16; o > 0; o >>= 1) p += __shfl_down_sync(0xffffffffu, p, o);
    return p;
}

__device__ __forceinline__ float sigmoidf_(float x) {
    return 1.0f / (1.0f + expf(-x));
}

__device__ __forceinline__ float dot4(float4 a, float4 b) {
    return a.x * b.x + a.y * b.y + a.z * b.z + a.w * b.w;
}

__device__ __forceinline__ void cp16(void* smem_dst, const void* gmem_src) {
    unsigned int s = (unsigned int)__cvta_generic_to_shared(smem_dst);
    asm volatile("cp.async.cg.shared.global [%0], [%1], 16;" :: "r"(s), "l"(gmem_src));
}
#define CP_COMMIT() asm volatile("cp.async.commit_group;")
#define CP_WAIT(n)  asm volatile("cp.async.wait_group %0;" :: "n"(n))

__device__ __forceinline__ void l2_prefetch(const void* p) {
    asm volatile("prefetch.global.L2 [%0];" :: "l"(p));
}

// score 32 rows (base..base+31): 8 warps x 4 rows, interleaved shfl chains
__device__ __forceinline__ void score_rows4(
    const float* tile, float4 wv, float bias, float* s_sh,
    int base, int wrp, int lane)
{
    float acc[4];
    #pragma unroll
    for (int t = 0; t < 4; t++) {
        const float4 rv = *(const float4*)&tile[(base + wrp + 8 * t) * HDIM + lane * 4];
        acc[t] = dot4(rv, wv);
    }
    #pragma unroll
    for (int o = 16; o > 0; o >>= 1) {
        #pragma unroll
        for (int t = 0; t < 4; t++)
            acc[t] += __shfl_down_sync(0xffffffffu, acc[t], o);
    }
    if (lane == 0) {
        #pragma unroll
        for (int t = 0; t < 4; t++)
            s_sh[base + wrp + 8 * t] = acc[t] + bias;
    }
}

// ---------------------------------------------------------------------------
// Attention (+ tail pre + tail warm). Blocks [0,NATT): 64-row cp.async tiles
// (32 KB, ~6 blocks/SM). [NATT,NATT+NPRE): hh-gate precompute (drain wave).
// [NATT+NPRE, +NWARM): L2-prefetch decode weights in the final drain.
// ---------------------------------------------------------------------------
__global__ void __launch_bounds__(256) attn_pre_kernel(
    const float* __restrict__ enc,
    const float* __restrict__ h0,
    const float* __restrict__ c0,
    const float* __restrict__ attW,
    const float* __restrict__ attb,
    const float* __restrict__ W_hh0,
    const float* __restrict__ b_ih0, const float* __restrict__ b_hh0,
    const float* __restrict__ W_hh1,
    const float* __restrict__ b_ih1, const float* __restrict__ b_hh1,
    const float* __restrict__ inp_W,
    const float* __restrict__ W_ih0,
    const float* __restrict__ W_ih1)
{
    const int tid  = threadIdx.x;
    const int lane = tid & 31;
    const int wrp  = tid >> 5;

    if (blockIdx.x >= NATT + NPRE) {
        // ---- warm block: prefetch decode weights into L2 ----
        const int wb = blockIdx.x - (NATT + NPRE);      // 0..15
        const int g  = wb * 256 + tid;                  // 0..4095 global thread
        // inp_W: 1024 lines of 32 floats
        if (g < 1024) l2_prefetch(inp_W + g * 32);
        // W_ih0: 2048 lines
        { const int l = g * 2;      // covers 0..8190 — guard below
          if (l < 2048)     l2_prefetch(W_ih0 + l * 32);
          if (l + 1 < 2048) l2_prefetch(W_ih0 + (l + 1) * 32); }
        // W_ih1: 2048 lines
        { const int l = g * 2;
          if (l < 2048)     l2_prefetch(W_ih1 + l * 32);
          if (l + 1 < 2048) l2_prefetch(W_ih1 + (l + 1) * 32); }
        return;
    }

    if (blockIdx.x >= NATT) {
        const int p  = blockIdx.x - NATT;
        const int b  = p >> 3;
        const int k0 = (p & 7) * 64;
        const float4 hv0 = ((const float4*)(h0 + b * HDIM))[lane];
        const float4 hv1 = ((const float4*)(h0 + BATCH * HDIM + b * HDIM))[lane];
        #pragma unroll 4
        for (int t = 0; t < 8; t++) {
            const int k = k0 + wrp * 8 + t;
            float p0 = dot4(((const float4*)(W_hh0 + k * HDIM))[lane], hv0);
            p0 = warp_sum(p0);
            if (lane == 0) g_pre0[b * 512 + k] = p0 + b_ih0[k] + b_hh0[k];
        }
        #pragma unroll 4
        for (int t = 0; t < 8; t++) {
            const int k = k0 + wrp * 8 + t;
            float p1 = dot4(((const float4*)(W_hh1 + k * HDIM))[lane], hv1);
            p1 = warp_sum(p1);
            if (lane == 0) g_pre1[b * 512 + k] = p1 + b_ih1[k] + b_hh1[k];
        }
        return;
    }

    extern __shared__ __align__(16) float tile[];   // 64*128 floats = 32 KB

    __shared__ float s_sh[CHUNK];
    __shared__ float e_sh[CHUNK];
    __shared__ float red[4];
    __shared__ float bias_sh;
    __shared__ float sprev_sh;
    __shared__ float part2[2][HDIM];

    const int chunk = blockIdx.x & (NCH - 1);
    const int b     = blockIdx.x >> 6;
    const int start = chunk * CHUNK;

    // Stage tile: 2048 float4, 8 per thread, 2 commit groups
    {
        const float4* src = (const float4*)(enc + ((size_t)b * WTOT + start) * HDIM);
        float4* dst = (float4*)tile;
        #pragma unroll
        for (int i = 0; i < 4; i++) cp16(&dst[tid + 256 * i], &src[tid + 256 * i]);
        CP_COMMIT();
        #pragma unroll
        for (int i = 4; i < 8; i++) cp16(&dst[tid + 256 * i], &src[tid + 256 * i]);
        CP_COMMIT();
    }

    float4 vprev = make_float4(0.f, 0.f, 0.f, 0.f);
    if (wrp == 0 && start > 0)
        vprev = ((const float4*)(enc + ((size_t)b * WTOT + start - 1) * HDIM))[lane];
    const float4 wv = ((const float4*)attW)[lane];

    if (tid < HDIM) {
        float p = h0[BATCH * HDIM + b * HDIM + tid]
                * c0[BATCH * HDIM + b * HDIM + tid]
                * attW[HDIM + tid];
        p = warp_sum(p);
        if (lane == 0) red[wrp] = p;
    }
    __syncthreads();
    if (tid == 0) bias_sh = red[0] + red[1] + red[2] + red[3] + attb[0];

    CP_WAIT(1);
    __syncthreads();
    const float bias = bias_sh;

    score_rows4(tile, wv, bias, s_sh, 0, wrp, lane);
    if (wrp == 0 && start > 0) {
        float s = warp_sum(dot4(vprev, wv));
        if (lane == 0) sprev_sh = s + bias;
    }

    CP_WAIT(0);
    __syncthreads();
    score_rows4(tile, wv, bias, s_sh, 32, wrp, lane);
    __syncthreads();

    if (tid < CHUNK) {
        float logit;
        if (tid == 0) logit = (start == 0) ? 0.0f : sprev_sh;
        else          logit = s_sh[tid - 1];
        e_sh[tid] = expf(logit);
    }
    __syncthreads();

    {
        const int h = tid & 127, grp = tid >> 7;
        float acc = 0.0f;
        #pragma unroll
        for (int j = 0; j < 32; j++) {
            const int r = grp * 32 + j;
            acc += e_sh[r] * tile[r * HDIM + h];
        }
        part2[grp][h] = acc;
    }
    __syncthreads();
    if (tid < HDIM)
        g_pvec[((size_t)b * NCH + chunk) * HDIM + tid] = part2[0][tid] + part2[1][tid];
    if (wrp == 0) {
        float es = e_sh[lane] + e_sh[lane + 32];
        es = warp_sum(es);
        if (lane == 0) g_psum[b * NCH + chunk] = es;
    }
}

// ---------------------------------------------------------------------------
// Pipelined coalesced warp-dots: 16 gates per warp, K=128.
// ---------------------------------------------------------------------------
__device__ __forceinline__ void lstm_gates(
    const float* __restrict__ W, const float4 xv,
    const float* __restrict__ pre_sh, float* gate_sh,
    int wrp, int lane)
{
    const int kbase = wrp * 16;
    float4 w[2][4];
    #pragma unroll
    for (int t = 0; t < 4; t++)
        w[0][t] = ((const float4*)(W + (kbase + t) * HDIM))[lane];
    #pragma unroll
    for (int g = 0; g < 4; g++) {
        if (g < 3) {
            #pragma unroll
            for (int t = 0; t < 4; t++)
                w[(g + 1) & 1][t] =
                    ((const float4*)(W + (kbase + (g + 1) * 4 + t) * HDIM))[lane];
        }
        float acc[4];
        #pragma unroll
        for (int t = 0; t < 4; t++) acc[t] = dot4(w[g & 1][t], xv);
        #pragma unroll
        for (int o = 16; o > 0; o >>= 1) {
            #pragma unroll
            for (int t = 0; t < 4; t++)
                acc[t] += __shfl_down_sync(0xffffffffu, acc[t], o);
        }
        if (lane == 0) {
            #pragma unroll
            for (int t = 0; t < 4; t++) {
                const int k = kbase + g * 4 + t;
                gate_sh[k] = acc[t] + pre_sh[k];
            }
        }
    }
}

// ---------------------------------------------------------------------------
// Decode (R14 structure + top-of-kernel L2 prefetch of all weights).
// ---------------------------------------------------------------------------
__global__ void __launch_bounds__(1024) decode_kernel(
    const float* __restrict__ input,
    const float* __restrict__ c0,
    const float* __restrict__ inp_W, const float* __restrict__ inp_b,
    const float* __restrict__ W_ih0,
    const float* __restrict__ W_ih1,
    float* __restrict__ out)
{
    __shared__ __align__(16) float cat_sh[256];
    __shared__ __align__(16) float xin_sh[HDIM];
    __shared__ __align__(16) float h1_sh[HDIM];
    __shared__ float gate_sh[512];
    __shared__ float c0_sh[2 * HDIM];
    __shared__ float vred[8][HDIM];
    __shared__ float sarr[NCH];
    __shared__ float pre0_sh[512];
    __shared__ float pre1_sh[512];
    __shared__ float S_sh;

    const int b = blockIdx.x;
    const int tid = threadIdx.x, lane = tid & 31, wrp = tid >> 5;

    // L2 prefetch of all decode weights (5 lines/thread, fire-and-forget).
    l2_prefetch(inp_W + tid * 32);                  // 1024 lines
    l2_prefetch(W_ih0 + (tid * 2) * 32);            // 2048 lines
    l2_prefetch(W_ih0 + (tid * 2 + 1) * 32);
    l2_prefetch(W_ih1 + (tid * 2) * 32);            // 2048 lines
    l2_prefetch(W_ih1 + (tid * 2 + 1) * 32);

    // Early independent loads
    if (tid < HDIM) {
        c0_sh[tid]        = c0[b * HDIM + tid];
        c0_sh[HDIM + tid] = c0[BATCH * HDIM + b * HDIM + tid];
    }
    if (tid < 512) pre0_sh[tid] = g_pre0[b * 512 + tid];
    else           pre1_sh[tid - 512] = g_pre1[b * 512 + (tid - 512)];

    // Stage 0: reduce attention partials — 8 groups x 8 chunks, distinct cells.
    if (tid < NCH) sarr[tid] = g_psum[b * NCH + tid];
    {
        const int h = tid & 127, grp = tid >> 7;
        float v = 0.0f;
        #pragma unroll
        for (int c = 0; c < 8; c++)
            v += g_pvec[((size_t)b * NCH + grp * 8 + c) * HDIM + h];
        vred[grp][h] = v;
    }
    __syncthreads();
    float vcol = 0.0f;
    if (tid < HDIM) {
        #pragma unroll
        for (int g = 0; g < 8; g++) vcol += vred[g][tid];
    }
    if (wrp == 0) {
        float s = sarr[lane] + sarr[lane + 32];
        s = warp_sum(s);
        if (lane == 0) S_sh = s;
    }
    __syncthreads();
    if (tid < HDIM) {
        cat_sh[tid]        = vcol / S_sh;
        cat_sh[HDIM + tid] = input[b * HDIM + tid];
    }
    __syncthreads();

    // xin: 32 warps x 4 outputs, K=256.
    {
        const float4 c0v = ((const float4*)cat_sh)[lane];
        const float4 c1v = ((const float4*)cat_sh)[lane + 32];
        float4 a0[4], a1[4];
        #pragma unroll
        for (int t = 0; t < 4; t++) {
            const float4* wrow = (const float4*)(inp_W + (wrp * 4 + t) * 256);
            a0[t] = wrow[lane];
            a1[t] = wrow[lane + 32];
        }
        float acc[4];
        #pragma unroll
        for (int t = 0; t < 4; t++)
            acc[t] = dot4(a0[t], c0v) + dot4(a1[t], c1v);
        #pragma unroll
        for (int o = 16; o > 0; o >>= 1) {
            #pragma unroll
            for (int t = 0; t < 4; t++)
                acc[t] += __shfl_down_sync(0xffffffffu, acc[t], o);
        }
        if (lane == 0) {
            #pragma unroll
            for (int t = 0; t < 4; t++) {
                const int i = wrp * 4 + t;
                xin_sh[i] = acc[t] + inp_b[i];
            }
        }
    }
    __syncthreads();

    float* out_h1 = out + 8192 + b * HDIM;
    float* out_h2 = out + 16384 + b * HDIM;
    float* out_c1 = out + 24576 + b * HDIM;
    float* out_c2 = out + 32768 + b * HDIM;
    float* out_y  = out + b * HDIM;

    // LSTM layer 0
    lstm_gates(W_ih0, ((const float4*)xin_sh)[lane], pre0_sh, gate_sh, wrp, lane);
    __syncthreads();
    if (tid < HDIM) {
        const float ig = gate_sh[tid];
        const float fg = gate_sh[128 + tid];
        const float gg = gate_sh[256 + tid];
        const float og = gate_sh[384 + tid];
        const float cn = sigmoidf_(fg) * c0_sh[tid] + sigmoidf_(ig) * tanhf(gg);
        const float hn = sigmoidf_(og) * tanhf(cn);
        h1_sh[tid]  = hn;
        out_c1[tid] = cn;
        out_h1[tid] = hn;
    }
    __syncthreads();

    // LSTM layer 1
    lstm_gates(W_ih1, ((const float4*)h1_sh)[lane], pre1_sh, gate_sh, wrp, lane);
    __syncthreads();
    if (tid < HDIM) {
        const float ig = gate_sh[tid];
        const float fg = gate_sh[128 + tid];
        const float gg = gate_sh[256 + tid];
        const float og = gate_sh[384 + tid];
        const float cn = sigmoidf_(fg) * c0_sh[HDIM + tid] + sigmoidf_(ig) * tanhf(gg);
        const float hn = sigmoidf_(og) * tanhf(cn);
        out_c2[tid] = cn;
        out_h2[tid] = hn;
        out_y[tid]  = hn;
    }
}

extern "C" void kernel_launch(void* const* d_in, const int* in_sizes, int n_in,
                              void* d_out, int out_size)
{
    const float* input  = (const float*)d_in[0];
    const float* h0     = (const float*)d_in[1];
    const float* c0     = (const float*)d_in[2];
    const float* enc    = (const float*)d_in[3];
    const float* attW   = (const float*)d_in[4];
    const float* attb   = (const float*)d_in[5];
    const float* inp_W  = (const float*)d_in[6];
    const float* inp_b  = (const float*)d_in[7];
    const float* W_ih0  = (const float*)d_in[8];
    const float* W_hh0  = (const float*)d_in[9];
    const float* b_ih0  = (const float*)d_in[10];
    const float* b_hh0  = (const float*)d_in[11];
    const float* W_ih1  = (const float*)d_in[12];
    const float* W_hh1  = (const float*)d_in[13];
    const float* b_ih1  = (const float*)d_in[14];
    const float* b_hh1  = (const float*)d_in[15];
    float* out = (float*)d_out;

    const int tile_bytes = CHUNK * HDIM * sizeof(float);   // 32 KB
    cudaFuncSetAttribute(attn_pre_kernel,
                         cudaFuncAttributeMaxDynamicSharedMemorySize, tile_bytes);

    attn_pre_kernel<<<NATT + NPRE + NWARM, 256, tile_bytes>>>(
        enc, h0, c0, attW, attb,
        W_hh0, b_ih0, b_hh0, W_hh1, b_ih1, b_hh1,
        inp_W, W_ih0, W_ih1);
    decode_kernel<<<BATCH, 1024>>>(input, c0, inp_W, inp_b, W_ih0, W_ih1, out);
}